// round 5
// baseline (speedup 1.0000x reference)
#include <cuda_runtime.h>
#include <cstdint>
#include <math.h>

#define B_ 16
#define L_ 2048
#define D_ 512
#define H_ 512

typedef unsigned long long ull;

// ---------------- static device scratch (no cudaMalloc allowed) -------------
__device__ float g_pre[(size_t)B_ * L_ * 1024];   // [b][t][fwd 0:512 | bwd 512:1024]
__device__ float g_hs [(size_t)B_ * L_ * 1024];   // same layout
__device__ float g_wxcat[512 * 1024];             // [k][n]  n<512: Wx_f, else Wx_b
__device__ float g_bcat[1024];
__device__ float g_wcomb[1024 * 512];             // rows 0:512 = Wo_f@Wd_top, 512:1024 = Wo_b@Wd_bot
__device__ float g_bias2[512];

// ---------------- f32x2 helpers ---------------------------------------------
__device__ __forceinline__ ull pk2(float x, float y) {
    ull r; asm("mov.b64 %0,{%1,%2};" : "=l"(r) : "f"(x), "f"(y)); return r;
}
__device__ __forceinline__ float2 up2(ull v) {
    float2 r; asm("mov.b64 {%0,%1},%2;" : "=f"(r.x), "=f"(r.y) : "l"(v)); return r;
}
__device__ __forceinline__ void fm2(ull& d, ull a, ull b) {
    asm("fma.rn.f32x2 %0,%1,%2,%0;" : "+l"(d) : "l"(a), "l"(b));
}

// ---------------- pack kernel: Wxcat / bcat ---------------------------------
__global__ void pack_kernel(const float* __restrict__ Wx_f, const float* __restrict__ Wx_b,
                            const float* __restrict__ b_f,  const float* __restrict__ b_b) {
    int idx = blockIdx.x * blockDim.x + threadIdx.x;   // 0 .. 524287
    int k = idx >> 10;
    int n = idx & 1023;
    g_wxcat[idx] = (n < 512) ? Wx_f[k * 512 + n] : Wx_b[k * 512 + (n - 512)];
    if (idx < 1024) g_bcat[idx] = (idx < 512) ? b_f[idx] : b_b[idx - 512];
}

// ---------------- bias2: fold bo_f, bo_b, bd through Wd ---------------------
__global__ void bias2_kernel(const float* __restrict__ Wd, const float* __restrict__ bd,
                             const float* __restrict__ bo_f, const float* __restrict__ bo_b) {
    int o = threadIdx.x;   // 512 threads
    float s = bd[o];
    for (int dd = 0; dd < 512; dd++) {
        s += bo_f[dd] * Wd[dd * 512 + o];
        s += bo_b[dd] * Wd[(512 + dd) * 512 + o];
    }
    g_bias2[o] = s;
}

// ---------------- generic SGEMM: C[m][n] = A[m][k]*B[k][n] + bias[n] --------
#define TBM 128
#define TBN 128
#define TBK 16
__global__ void __launch_bounds__(256, 2)
sgemm(const float* __restrict__ A, const float* __restrict__ B,
      const float* __restrict__ bias, float* __restrict__ C,
      int M, int N, int K) {
    __shared__ float As[TBK][TBM + 4];
    __shared__ float Bs[TBK][TBN + 4];

    int tid = threadIdx.x;
    int bx = blockIdx.x, by = blockIdx.y;
    int tx = tid & 15, ty = tid >> 4;

    int mA  = tid >> 2;       // 0..63 (two rows: mA, mA+64)
    int kcA = tid & 3;        // float4 chunk along K
    int kbB = tid >> 5;       // 0..7 (two rows: kbB, kbB+8)
    int ncB = tid & 31;       // float4 chunk along N

    ull acc[8][4];
    #pragma unroll
    for (int i = 0; i < 8; i++)
        #pragma unroll
        for (int j = 0; j < 4; j++) acc[i][j] = 0ull;

    const float* Ag = A + (size_t)(by * TBM + mA) * K + kcA * 4;
    const float* Bg = B + (size_t)kbB * N + bx * TBN + ncB * 4;

    for (int k0 = 0; k0 < K; k0 += TBK) {
        float4 a0 = *(const float4*)(Ag + k0);
        float4 a1 = *(const float4*)(Ag + (size_t)64 * K + k0);
        float4 b0 = *(const float4*)(Bg + (size_t)k0 * N);
        float4 b1 = *(const float4*)(Bg + (size_t)(k0 + 8) * N);

        __syncthreads();
        As[kcA * 4 + 0][mA] = a0.x;  As[kcA * 4 + 1][mA] = a0.y;
        As[kcA * 4 + 2][mA] = a0.z;  As[kcA * 4 + 3][mA] = a0.w;
        As[kcA * 4 + 0][mA + 64] = a1.x;  As[kcA * 4 + 1][mA + 64] = a1.y;
        As[kcA * 4 + 2][mA + 64] = a1.z;  As[kcA * 4 + 3][mA + 64] = a1.w;
        *(float4*)&Bs[kbB][ncB * 4]     = b0;
        *(float4*)&Bs[kbB + 8][ncB * 4] = b1;
        __syncthreads();

        #pragma unroll
        for (int kk = 0; kk < TBK; kk++) {
            float4 al = *(float4*)&As[kk][ty * 8];
            float4 ah = *(float4*)&As[kk][ty * 8 + 4];
            float4 bl = *(float4*)&Bs[kk][tx * 8];
            float4 bh = *(float4*)&Bs[kk][tx * 8 + 4];
            ull bb[4] = { pk2(bl.x, bl.y), pk2(bl.z, bl.w),
                          pk2(bh.x, bh.y), pk2(bh.z, bh.w) };
            float av[8] = { al.x, al.y, al.z, al.w, ah.x, ah.y, ah.z, ah.w };
            #pragma unroll
            for (int i = 0; i < 8; i++) {
                ull ad = pk2(av[i], av[i]);
                #pragma unroll
                for (int jn = 0; jn < 4; jn++) fm2(acc[i][jn], ad, bb[jn]);
            }
        }
    }

    int mBase = by * TBM + ty * 8;
    int nBase = bx * TBN + tx * 8;
    float4 bvl = make_float4(0.f, 0.f, 0.f, 0.f), bvh = bvl;
    if (bias) {
        bvl = *(const float4*)(bias + nBase);
        bvh = *(const float4*)(bias + nBase + 4);
    }
    #pragma unroll
    for (int i = 0; i < 8; i++) {
        float2 p0 = up2(acc[i][0]), p1 = up2(acc[i][1]);
        float2 p2 = up2(acc[i][2]), p3 = up2(acc[i][3]);
        float4 c0 = make_float4(p0.x + bvl.x, p0.y + bvl.y, p1.x + bvl.z, p1.y + bvl.w);
        float4 c1 = make_float4(p2.x + bvh.x, p2.y + bvh.y, p3.x + bvh.z, p3.y + bvh.w);
        float* cp = C + (size_t)(mBase + i) * N + nBase;
        *(float4*)cp = c0;
        *(float4*)(cp + 4) = c1;
    }
}

// ---------------- recurrence: 16 clusters x 8 CTAs --------------------------
// Thread (warp wp, lane l): kseg = l&7 (k range [64*kseg,+64)), jl = wp*4+(l>>3).
// Weights in registers. Reduce via 3x shfl.xor (all 8 lanes get the sum).
// Lane kseg=p pushes h[jg] to peer CTA p via PLAIN st.shared::cluster.
// Sync: distributed mbarrier barrier, ONE arrive.release.cluster per CTA-pair
// per step (count=8), double-buffered by step parity. No barrier.cluster,
// no tx counting, no L1D flush in the loop.

__device__ __forceinline__ void cluster_sync_() {
    asm volatile("barrier.cluster.arrive.aligned;" ::: "memory");
    asm volatile("barrier.cluster.wait.aligned;" ::: "memory");
}
__device__ __forceinline__ void st_cluster_f32(uint32_t raddr, float v) {
    asm volatile("st.shared::cluster.f32 [%0], %1;" :: "r"(raddr), "f"(v) : "memory");
}
__device__ __forceinline__ void mbar_arrive_cluster(uint32_t raddr) {
    asm volatile("mbarrier.arrive.release.cluster.shared::cluster.b64 _, [%0];"
                 :: "r"(raddr) : "memory");
}
__device__ __forceinline__ void mbar_wait_cluster(uint32_t mbar, uint32_t parity) {
    uint32_t done;
    asm volatile("{\n\t.reg .pred p;\n\t"
                 "mbarrier.try_wait.parity.acquire.cluster.shared::cta.b64 p, [%1], %2;\n\t"
                 "selp.b32 %0, 1, 0, p;\n\t}"
                 : "=r"(done) : "r"(mbar), "r"(parity) : "memory");
    if (!done) {
        asm volatile("{\n\t.reg .pred P1;\n\t"
                     "WL_%=:\n\t"
                     "mbarrier.try_wait.parity.acquire.cluster.shared::cta.b64 P1, [%0], %1, 0x989680;\n\t"
                     "@P1 bra.uni WD_%=;\n\t"
                     "bra.uni WL_%=;\n\t"
                     "WD_%=:\n\t}"
                     :: "r"(mbar), "r"(parity) : "memory");
    }
}

__global__ void __launch_bounds__(512, 1) __cluster_dims__(8, 1, 1)
rnn_scan(const float* __restrict__ Wh_f, const float* __restrict__ Wh_b) {
    __shared__ __align__(16) float hbuf[2176];   // [buf2][batch2][544=8*68]
    __shared__ __align__(16) ull mb[2];

    int tid  = threadIdx.x;
    int bid  = blockIdx.x;
    int rank = bid & 7;
    int cid  = bid >> 3;
    int dir  = cid >> 3;
    int pair = cid & 7;
    int b0   = pair * 2;
    int jbase = rank * 64;
    const float* __restrict__ Wh = dir ? Wh_b : Wh_f;

    int l    = tid & 31, wp = tid >> 5;
    int kseg = l & 7;
    int jl   = wp * 4 + (l >> 3);
    int jg   = jbase + jl;
    int k0   = kseg * 64;

    // weights: 32 packed (k,k+1) pairs for column jg, k in [k0, k0+64)
    ull w[32];
    #pragma unroll
    for (int c = 0; c < 32; c++)
        w[c] = pk2(__ldg(&Wh[(size_t)(k0 + 2*c) * H_ + jg]),
                   __ldg(&Wh[(size_t)(k0 + 2*c + 1) * H_ + jg]));

    for (int i = tid; i < 2176; i += 512) hbuf[i] = 0.f;

    uint32_t hb_s = (uint32_t)__cvta_generic_to_shared(hbuf);
    uint32_t mb_s = (uint32_t)__cvta_generic_to_shared(mb);

    if (tid == 0) {
        asm volatile("mbarrier.init.shared.b64 [%0], 8;" :: "r"(mb_s)     : "memory");
        asm volatile("mbarrier.init.shared.b64 [%0], 8;" :: "r"(mb_s + 8) : "memory");
    }
    __syncthreads();
    cluster_sync_();   // barriers initialized before any remote arrive

    // peer smem bases (mapa preserves intra-CTA offsets)
    uint32_t pb[8];
    #pragma unroll
    for (int r = 0; r < 8; r++)
        asm("mapa.shared::cluster.u32 %0, %1, %2;" : "=r"(pb[r]) : "r"(hb_s), "r"(r));
    uint32_t dmb = mb_s - hb_s;

    const float* pre0 = &g_pre[(size_t)b0       * L_ * 1024 + dir * 512 + jg];
    const float* pre1 = &g_pre[(size_t)(b0 + 1) * L_ * 1024 + dir * 512 + jg];
    int t0 = dir ? (L_ - 1) : 0;
    float pv0 = __ldg(pre0 + (size_t)t0 * 1024);
    float pv1 = __ldg(pre1 + (size_t)t0 * 1024);
    // position of my output column in every CTA's hbuf (k-index == jg)
    uint32_t pj4 = (uint32_t)(((jg >> 6) * 68 + (jg & 63)) * 4);

    float* hs0 = &g_hs[(size_t)b0       * L_ * 1024 + dir * 512 + jg];
    float* hs1 = &g_hs[(size_t)(b0 + 1) * L_ * 1024 + dir * 512 + jg];

    for (int s = 0; s < L_; s++) {
        int t = dir ? (L_ - 1 - s) : s;
        if (s) mbar_wait_cluster(mb_s + 8 * (s & 1), ((s - 1) >> 1) & 1);

        // prefetch next step's pre (hidden under compute)
        float nv0 = 0.f, nv1 = 0.f;
        if (s + 1 < L_) {
            int tn = dir ? (L_ - 2 - s) : (s + 1);
            nv0 = __ldg(pre0 + (size_t)tn * 1024);
            nv1 = __ldg(pre1 + (size_t)tn * 1024);
        }

        const float* h0p = hbuf + (s & 1) * 1088 + kseg * 68;  // batch 0
        const float* h1p = h0p + 544;                          // batch 1
        ull a0 = 0ull, a1 = 0ull, a2 = 0ull, a3 = 0ull;
        #pragma unroll
        for (int c = 0; c < 16; c++) {
            float4 ha = *(const float4*)(h0p + 4 * c);
            float4 hb = *(const float4*)(h1p + 4 * c);
            fm2(a0, w[2*c],     pk2(ha.x, ha.y));
            fm2(a1, w[2*c + 1], pk2(ha.z, ha.w));
            fm2(a2, w[2*c],     pk2(hb.x, hb.y));
            fm2(a3, w[2*c + 1], pk2(hb.z, hb.w));
        }
        float2 u0 = up2(a0), u1 = up2(a1), u2 = up2(a2), u3 = up2(a3);
        float r0 = (u0.x + u0.y) + (u1.x + u1.y);
        float r1 = (u2.x + u2.y) + (u3.x + u3.y);
        r0 += __shfl_xor_sync(0xffffffffu, r0, 1);
        r1 += __shfl_xor_sync(0xffffffffu, r1, 1);
        r0 += __shfl_xor_sync(0xffffffffu, r0, 2);
        r1 += __shfl_xor_sync(0xffffffffu, r1, 2);
        r0 += __shfl_xor_sync(0xffffffffu, r0, 4);
        r1 += __shfl_xor_sync(0xffffffffu, r1, 4);
        // all 8 lanes of the group now hold the full dot products
        float hn0 = tanhf(r0 + pv0);
        float hn1 = tanhf(r1 + pv1);

        if (kseg == 0) {           // one lane per (j,batch) writes history
            hs0[(size_t)t * 1024] = hn0;
            hs1[(size_t)t * 1024] = hn1;
        }

        if (s + 1 < L_) {
            uint32_t nxt  = (uint32_t)((s + 1) & 1);
            uint32_t offb = nxt * 1088 * 4 + pj4;
            // lane kseg==p delivers to cluster CTA p (self included)
            st_cluster_f32(pb[kseg] + offb,           hn0);
            st_cluster_f32(pb[kseg] + offb + 544 * 4, hn1);
            __syncthreads();
            if (tid < 8) mbar_arrive_cluster(pb[tid] + dmb + 8 * nxt);
        }
        pv0 = nv0; pv1 = nv1;
    }
    cluster_sync_();   // exit safety: no CTA leaves while peers may still touch it
}

// ---------------- host ------------------------------------------------------
extern "C" void kernel_launch(void* const* d_in, const int* in_sizes, int n_in,
                              void* d_out, int out_size) {
    const float* x    = (const float*)d_in[0];
    // d_in[1] = c (unused by reference)
    const float* Wx_f = (const float*)d_in[2];
    const float* Wh_f = (const float*)d_in[3];
    const float* b_f  = (const float*)d_in[4];
    const float* Wo_f = (const float*)d_in[5];
    const float* bo_f = (const float*)d_in[6];
    const float* Wx_b = (const float*)d_in[7];
    const float* Wh_b = (const float*)d_in[8];
    const float* b_b  = (const float*)d_in[9];
    const float* Wo_b = (const float*)d_in[10];
    const float* bo_b = (const float*)d_in[11];
    const float* Wd   = (const float*)d_in[12];
    const float* bd   = (const float*)d_in[13];
    float* out = (float*)d_out;

    void *p_pre, *p_hs, *p_wx, *p_bc, *p_wc, *p_b2;
    cudaGetSymbolAddress(&p_pre, g_pre);
    cudaGetSymbolAddress(&p_hs,  g_hs);
    cudaGetSymbolAddress(&p_wx,  g_wxcat);
    cudaGetSymbolAddress(&p_bc,  g_bcat);
    cudaGetSymbolAddress(&p_wc,  g_wcomb);
    cudaGetSymbolAddress(&p_b2,  g_bias2);

    // 1) pack Wx / biases
    pack_kernel<<<1024, 512>>>(Wx_f, Wx_b, b_f, b_b);

    // 2) pre = x @ Wxcat + bcat     [32768,512]@[512,1024]
    {
        dim3 g(1024 / TBN, (B_ * L_) / TBM);
        sgemm<<<g, 256>>>(x, (const float*)p_wx, (const float*)p_bc,
                          (float*)p_pre, B_ * L_, 1024, 512);
    }

    // 3) bidirectional scan (3rd launch -> ncu capture window)
    {
        cudaLaunchConfig_t cfg = {};
        cfg.gridDim = dim3(128, 1, 1);
        cfg.blockDim = dim3(512, 1, 1);
        cfg.dynamicSmemBytes = 0;
        cfg.stream = 0;
        cudaLaunchAttribute at[1];
        at[0].id = cudaLaunchAttributeClusterDimension;
        at[0].val.clusterDim.x = 8; at[0].val.clusterDim.y = 1; at[0].val.clusterDim.z = 1;
        cfg.attrs = at;
        cfg.numAttrs = 1;
        cudaLaunchKernelEx(&cfg, rnn_scan, Wh_f, Wh_b);
    }

    // 4) Wcomb = [Wo_f@Wd_top ; Wo_b@Wd_bot], bias2
    {
        dim3 g(512 / TBN, 512 / TBM);
        sgemm<<<g, 256>>>(Wo_f, Wd, nullptr, (float*)p_wc, 512, 512, 512);
        sgemm<<<g, 256>>>(Wo_b, Wd + 512 * 512, nullptr,
                          (float*)p_wc + 512 * 512, 512, 512, 512);
    }
    bias2_kernel<<<1, 512>>>(Wd, bd, bo_f, bo_b);

    // 5) out = hs @ Wcomb + bias2   [32768,1024]@[1024,512]
    {
        dim3 g(512 / TBN, (B_ * L_) / TBM);
        sgemm<<<g, 256>>>((const float*)p_hs, (const float*)p_wc,
                          (const float*)p_b2, out, B_ * L_, 512, 1024);
    }
}

// round 6
// speedup vs baseline: 1.0374x; 1.0374x over previous
#include <cuda_runtime.h>
#include <cstdint>
#include <math.h>

#define B_ 16
#define L_ 2048
#define D_ 512
#define H_ 512

typedef unsigned long long ull;

// ---------------- static device scratch (no cudaMalloc allowed) -------------
__device__ float g_pre[(size_t)B_ * L_ * 1024];   // [b][t][fwd 0:512 | bwd 512:1024]
__device__ float g_hs [(size_t)B_ * L_ * 1024];   // same layout
__device__ float g_wxcat[512 * 1024];             // [k][n]  n<512: Wx_f, else Wx_b
__device__ float g_bcat[1024];
__device__ float g_wcomb[1024 * 512];             // rows 0:512 = Wo_f@Wd_top, 512:1024 = Wo_b@Wd_bot
__device__ float g_bias2[512];

// ---------------- f32x2 helpers ---------------------------------------------
__device__ __forceinline__ ull pk2(float x, float y) {
    ull r; asm("mov.b64 %0,{%1,%2};" : "=l"(r) : "f"(x), "f"(y)); return r;
}
__device__ __forceinline__ float2 up2(ull v) {
    float2 r; asm("mov.b64 {%0,%1},%2;" : "=f"(r.x), "=f"(r.y) : "l"(v)); return r;
}
__device__ __forceinline__ void fm2(ull& d, ull a, ull b) {
    asm("fma.rn.f32x2 %0,%1,%2,%0;" : "+l"(d) : "l"(a), "l"(b));
}

// ---------------- pack kernel: Wxcat / bcat ---------------------------------
__global__ void pack_kernel(const float* __restrict__ Wx_f, const float* __restrict__ Wx_b,
                            const float* __restrict__ b_f,  const float* __restrict__ b_b) {
    int idx = blockIdx.x * blockDim.x + threadIdx.x;   // 0 .. 524287
    int k = idx >> 10;
    int n = idx & 1023;
    g_wxcat[idx] = (n < 512) ? Wx_f[k * 512 + n] : Wx_b[k * 512 + (n - 512)];
    if (idx < 1024) g_bcat[idx] = (idx < 512) ? b_f[idx] : b_b[idx - 512];
}

// ---------------- bias2: fold bo_f, bo_b, bd through Wd ---------------------
__global__ void bias2_kernel(const float* __restrict__ Wd, const float* __restrict__ bd,
                             const float* __restrict__ bo_f, const float* __restrict__ bo_b) {
    int o = threadIdx.x;   // 512 threads
    float s = bd[o];
    for (int dd = 0; dd < 512; dd++) {
        s += bo_f[dd] * Wd[dd * 512 + o];
        s += bo_b[dd] * Wd[(512 + dd) * 512 + o];
    }
    g_bias2[o] = s;
}

// ---------------- generic SGEMM: C[m][n] = A[m][k]*B[k][n] + bias[n] --------
#define TBM 128
#define TBN 128
#define TBK 16
__global__ void __launch_bounds__(256, 2)
sgemm(const float* __restrict__ A, const float* __restrict__ B,
      const float* __restrict__ bias, float* __restrict__ C,
      int M, int N, int K) {
    __shared__ float As[TBK][TBM + 4];
    __shared__ float Bs[TBK][TBN + 4];

    int tid = threadIdx.x;
    int bx = blockIdx.x, by = blockIdx.y;
    int tx = tid & 15, ty = tid >> 4;

    int mA  = tid >> 2;       // 0..63 (two rows: mA, mA+64)
    int kcA = tid & 3;        // float4 chunk along K
    int kbB = tid >> 5;       // 0..7 (two rows: kbB, kbB+8)
    int ncB = tid & 31;       // float4 chunk along N

    ull acc[8][4];
    #pragma unroll
    for (int i = 0; i < 8; i++)
        #pragma unroll
        for (int j = 0; j < 4; j++) acc[i][j] = 0ull;

    const float* Ag = A + (size_t)(by * TBM + mA) * K + kcA * 4;
    const float* Bg = B + (size_t)kbB * N + bx * TBN + ncB * 4;

    for (int k0 = 0; k0 < K; k0 += TBK) {
        float4 a0 = *(const float4*)(Ag + k0);
        float4 a1 = *(const float4*)(Ag + (size_t)64 * K + k0);
        float4 b0 = *(const float4*)(Bg + (size_t)k0 * N);
        float4 b1 = *(const float4*)(Bg + (size_t)(k0 + 8) * N);

        __syncthreads();
        As[kcA * 4 + 0][mA] = a0.x;  As[kcA * 4 + 1][mA] = a0.y;
        As[kcA * 4 + 2][mA] = a0.z;  As[kcA * 4 + 3][mA] = a0.w;
        As[kcA * 4 + 0][mA + 64] = a1.x;  As[kcA * 4 + 1][mA + 64] = a1.y;
        As[kcA * 4 + 2][mA + 64] = a1.z;  As[kcA * 4 + 3][mA + 64] = a1.w;
        *(float4*)&Bs[kbB][ncB * 4]     = b0;
        *(float4*)&Bs[kbB + 8][ncB * 4] = b1;
        __syncthreads();

        #pragma unroll
        for (int kk = 0; kk < TBK; kk++) {
            float4 al = *(float4*)&As[kk][ty * 8];
            float4 ah = *(float4*)&As[kk][ty * 8 + 4];
            float4 bl = *(float4*)&Bs[kk][tx * 8];
            float4 bh = *(float4*)&Bs[kk][tx * 8 + 4];
            ull bb[4] = { pk2(bl.x, bl.y), pk2(bl.z, bl.w),
                          pk2(bh.x, bh.y), pk2(bh.z, bh.w) };
            float av[8] = { al.x, al.y, al.z, al.w, ah.x, ah.y, ah.z, ah.w };
            #pragma unroll
            for (int i = 0; i < 8; i++) {
                ull ad = pk2(av[i], av[i]);
                #pragma unroll
                for (int jn = 0; jn < 4; jn++) fm2(acc[i][jn], ad, bb[jn]);
            }
        }
    }

    int mBase = by * TBM + ty * 8;
    int nBase = bx * TBN + tx * 8;
    float4 bvl = make_float4(0.f, 0.f, 0.f, 0.f), bvh = bvl;
    if (bias) {
        bvl = *(const float4*)(bias + nBase);
        bvh = *(const float4*)(bias + nBase + 4);
    }
    #pragma unroll
    for (int i = 0; i < 8; i++) {
        float2 p0 = up2(acc[i][0]), p1 = up2(acc[i][1]);
        float2 p2 = up2(acc[i][2]), p3 = up2(acc[i][3]);
        float4 c0 = make_float4(p0.x + bvl.x, p0.y + bvl.y, p1.x + bvl.z, p1.y + bvl.w);
        float4 c1 = make_float4(p2.x + bvh.x, p2.y + bvh.y, p3.x + bvh.z, p3.y + bvh.w);
        float* cp = C + (size_t)(mBase + i) * N + nBase;
        *(float4*)cp = c0;
        *(float4*)(cp + 4) = c1;
    }
}

// ---------------- recurrence: 16 clusters x 8 CTAs --------------------------
// Thread (warp wp, lane l): kseg = l&7 (k range [64*kseg,+64)), jl = wp*4+(l>>3).
// Weights in registers (32 packed f32x2). Reduce via 3x shfl.xor -> ALL 8
// lanes hold the result; lane kseg=p pushes h[jg] to cluster CTA p via plain
// st.shared::cluster (self included). Sync = barrier.cluster per step (the
// arrive releases each thread's own remote stores; wait acquires them). No
// __syncthreads, no part[] SMEM, no serialized phase. pre-prefetch issued
// between arrive and wait to hide DRAM latency inside the rendezvous.

__device__ __forceinline__ void st_cluster_f32(uint32_t raddr, float v) {
    asm volatile("st.shared::cluster.f32 [%0], %1;" :: "r"(raddr), "f"(v) : "memory");
}

__global__ void __launch_bounds__(512, 1) __cluster_dims__(8, 1, 1)
rnn_scan(const float* __restrict__ Wh_f, const float* __restrict__ Wh_b) {
    __shared__ __align__(16) float hbuf[2176];   // [buf2][batch2][544=8*68]

    int tid  = threadIdx.x;
    int bid  = blockIdx.x;
    int rank = bid & 7;
    int cid  = bid >> 3;
    int dir  = cid >> 3;
    int pair = cid & 7;
    int b0   = pair * 2;
    int jbase = rank * 64;
    const float* __restrict__ Wh = dir ? Wh_b : Wh_f;

    int l    = tid & 31, wp = tid >> 5;
    int kseg = l & 7;
    int jl   = wp * 4 + (l >> 3);
    int jg   = jbase + jl;
    int k0   = kseg * 64;

    // weights: 32 packed (k,k+1) pairs for column jg, k in [k0, k0+64)
    ull w[32];
    #pragma unroll
    for (int c = 0; c < 32; c++)
        w[c] = pk2(__ldg(&Wh[(size_t)(k0 + 2*c) * H_ + jg]),
                   __ldg(&Wh[(size_t)(k0 + 2*c + 1) * H_ + jg]));

    for (int i = tid; i < 2176; i += 512) hbuf[i] = 0.f;
    __syncthreads();

    uint32_t hb_s = (uint32_t)__cvta_generic_to_shared(hbuf);
    // peer hbuf base for MY kseg's target CTA (mapa preserves offsets)
    uint32_t pbk;
    asm("mapa.shared::cluster.u32 %0, %1, %2;" : "=r"(pbk) : "r"(hb_s), "r"(kseg));
    // position of my output column jg in every CTA's hbuf (k-index == jg)
    uint32_t pj4 = (uint32_t)(((jg >> 6) * 68 + (jg & 63)) * 4);

    const float* pre0 = &g_pre[(size_t)b0       * L_ * 1024 + dir * 512 + jg];
    const float* pre1 = &g_pre[(size_t)(b0 + 1) * L_ * 1024 + dir * 512 + jg];
    float* hs0 = &g_hs[(size_t)b0       * L_ * 1024 + dir * 512 + jg];
    float* hs1 = &g_hs[(size_t)(b0 + 1) * L_ * 1024 + dir * 512 + jg];

    int t0 = dir ? (L_ - 1) : 0;
    float pv0 = __ldg(pre0 + (size_t)t0 * 1024);
    float pv1 = __ldg(pre1 + (size_t)t0 * 1024);

    // initial rendezvous: hbuf zeros visible cluster-wide
    asm volatile("barrier.cluster.arrive.aligned;" ::: "memory");
    asm volatile("barrier.cluster.wait.aligned;"   ::: "memory");

    for (int s = 0; s < L_; s++) {
        int t = dir ? (L_ - 1 - s) : s;

        const float* h0p = hbuf + (s & 1) * 1088 + kseg * 68;  // batch 0
        const float* h1p = h0p + 544;                          // batch 1
        ull a0 = 0ull, a1 = 0ull, a2 = 0ull, a3 = 0ull;
        #pragma unroll
        for (int c = 0; c < 16; c++) {
            ulonglong2 ha = *(const ulonglong2*)(h0p + 4 * c);
            ulonglong2 hb = *(const ulonglong2*)(h1p + 4 * c);
            fm2(a0, w[2*c],     ha.x);
            fm2(a1, w[2*c + 1], ha.y);
            fm2(a2, w[2*c],     hb.x);
            fm2(a3, w[2*c + 1], hb.y);
        }
        float2 u0 = up2(a0), u1 = up2(a1), u2 = up2(a2), u3 = up2(a3);
        float r0 = (u0.x + u0.y) + (u1.x + u1.y);
        float r1 = (u2.x + u2.y) + (u3.x + u3.y);
        r0 += __shfl_xor_sync(0xffffffffu, r0, 1);
        r1 += __shfl_xor_sync(0xffffffffu, r1, 1);
        r0 += __shfl_xor_sync(0xffffffffu, r0, 2);
        r1 += __shfl_xor_sync(0xffffffffu, r1, 2);
        r0 += __shfl_xor_sync(0xffffffffu, r0, 4);
        r1 += __shfl_xor_sync(0xffffffffu, r1, 4);
        // all 8 lanes of the group now hold the full dot products
        float hn0 = tanhf(r0 + pv0);
        float hn1 = tanhf(r1 + pv1);

        if (kseg == 0) {           // one lane per (j,batch) writes history
            hs0[(size_t)t * 1024] = hn0;
            hs1[(size_t)t * 1024] = hn1;
        }

        if (s + 1 < L_) {
            uint32_t offb = (uint32_t)(((s + 1) & 1) * 1088 * 4) + pj4;
            // lane kseg==p delivers h[jg] into CTA p's next buffer
            st_cluster_f32(pbk + offb,           hn0);
            st_cluster_f32(pbk + offb + 544 * 4, hn1);

            // arrive releases this thread's stores; prefetch hides in window
            asm volatile("barrier.cluster.arrive.aligned;" ::: "memory");
            int tn = dir ? (L_ - 2 - s) : (s + 1);
            pv0 = __ldg(pre0 + (size_t)tn * 1024);
            pv1 = __ldg(pre1 + (size_t)tn * 1024);
            asm volatile("barrier.cluster.wait.aligned;" ::: "memory");
        }
    }
    // exit safety: no CTA leaves while peers may still write into it
    asm volatile("barrier.cluster.arrive.aligned;" ::: "memory");
    asm volatile("barrier.cluster.wait.aligned;"   ::: "memory");
}

// ---------------- host ------------------------------------------------------
extern "C" void kernel_launch(void* const* d_in, const int* in_sizes, int n_in,
                              void* d_out, int out_size) {
    const float* x    = (const float*)d_in[0];
    // d_in[1] = c (unused by reference)
    const float* Wx_f = (const float*)d_in[2];
    const float* Wh_f = (const float*)d_in[3];
    const float* b_f  = (const float*)d_in[4];
    const float* Wo_f = (const float*)d_in[5];
    const float* bo_f = (const float*)d_in[6];
    const float* Wx_b = (const float*)d_in[7];
    const float* Wh_b = (const float*)d_in[8];
    const float* b_b  = (const float*)d_in[9];
    const float* Wo_b = (const float*)d_in[10];
    const float* bo_b = (const float*)d_in[11];
    const float* Wd   = (const float*)d_in[12];
    const float* bd   = (const float*)d_in[13];
    float* out = (float*)d_out;

    void *p_pre, *p_hs, *p_wx, *p_bc, *p_wc, *p_b2;
    cudaGetSymbolAddress(&p_pre, g_pre);
    cudaGetSymbolAddress(&p_hs,  g_hs);
    cudaGetSymbolAddress(&p_wx,  g_wxcat);
    cudaGetSymbolAddress(&p_bc,  g_bcat);
    cudaGetSymbolAddress(&p_wc,  g_wcomb);
    cudaGetSymbolAddress(&p_b2,  g_bias2);

    // launch order puts the scan at index 5 (6th) -> ncu -s 5 -c 1 captures it

    // 0) pack Wx / biases
    pack_kernel<<<1024, 512>>>(Wx_f, Wx_b, b_f, b_b);

    // 1) pre = x @ Wxcat + bcat     [32768,512]@[512,1024]
    {
        dim3 g(1024 / TBN, (B_ * L_) / TBM);
        sgemm<<<g, 256>>>(x, (const float*)p_wx, (const float*)p_bc,
                          (float*)p_pre, B_ * L_, 1024, 512);
    }

    // 2,3) Wcomb = [Wo_f@Wd_top ; Wo_b@Wd_bot]
    {
        dim3 g(512 / TBN, 512 / TBM);
        sgemm<<<g, 256>>>(Wo_f, Wd, nullptr, (float*)p_wc, 512, 512, 512);
        sgemm<<<g, 256>>>(Wo_b, Wd + 512 * 512, nullptr,
                          (float*)p_wc + 512 * 512, 512, 512, 512);
    }
    // 4) bias2
    bias2_kernel<<<1, 512>>>(Wd, bd, bo_f, bo_b);

    // 5) bidirectional scan
    {
        cudaLaunchConfig_t cfg = {};
        cfg.gridDim = dim3(128, 1, 1);
        cfg.blockDim = dim3(512, 1, 1);
        cfg.dynamicSmemBytes = 0;
        cfg.stream = 0;
        cudaLaunchAttribute at[1];
        at[0].id = cudaLaunchAttributeClusterDimension;
        at[0].val.clusterDim.x = 8; at[0].val.clusterDim.y = 1; at[0].val.clusterDim.z = 1;
        cfg.attrs = at;
        cfg.numAttrs = 1;
        cudaLaunchKernelEx(&cfg, rnn_scan, Wh_f, Wh_b);
    }

    // 6) out = hs @ Wcomb + bias2   [32768,1024]@[1024,512]
    {
        dim3 g(512 / TBN, (B_ * L_) / TBM);
        sgemm<<<g, 256>>>((const float*)p_hs, (const float*)p_wc,
                          (const float*)p_b2, out, B_ * L_, 512, 1024);
    }
}

// round 7
// speedup vs baseline: 1.7755x; 1.7114x over previous
#include <cuda_runtime.h>
#include <cstdint>
#include <math.h>

#define B_ 16
#define L_ 2048
#define D_ 512
#define H_ 512

typedef unsigned long long ull;

// ---------------- static device scratch (no cudaMalloc allowed) -------------
__device__ float g_pre[(size_t)B_ * L_ * 1024];   // [b][t][fwd 0:512 | bwd 512:1024]
__device__ float g_hs [(size_t)B_ * L_ * 1024];   // same layout
__device__ float g_wxcat[512 * 1024];             // [k][n]  n<512: Wx_f, else Wx_b
__device__ float g_bcat[1024];
__device__ float g_wcomb[1024 * 512];             // rows 0:512 = Wo_f@Wd_top, 512:1024 = Wo_b@Wd_bot
__device__ float g_bias2[512];

// ---------------- f32x2 helpers ---------------------------------------------
__device__ __forceinline__ ull pk2(float x, float y) {
    ull r; asm("mov.b64 %0,{%1,%2};" : "=l"(r) : "f"(x), "f"(y)); return r;
}
__device__ __forceinline__ float2 up2(ull v) {
    float2 r; asm("mov.b64 {%0,%1},%2;" : "=f"(r.x), "=f"(r.y) : "l"(v)); return r;
}
__device__ __forceinline__ void fm2(ull& d, ull a, ull b) {
    asm("fma.rn.f32x2 %0,%1,%2,%0;" : "+l"(d) : "l"(a), "l"(b));
}

// ---------------- pack kernel: Wxcat / bcat ---------------------------------
__global__ void pack_kernel(const float* __restrict__ Wx_f, const float* __restrict__ Wx_b,
                            const float* __restrict__ b_f,  const float* __restrict__ b_b) {
    int idx = blockIdx.x * blockDim.x + threadIdx.x;   // 0 .. 524287
    int k = idx >> 10;
    int n = idx & 1023;
    g_wxcat[idx] = (n < 512) ? Wx_f[k * 512 + n] : Wx_b[k * 512 + (n - 512)];
    if (idx < 1024) g_bcat[idx] = (idx < 512) ? b_f[idx] : b_b[idx - 512];
}

// ---------------- bias2: fold bo_f, bo_b, bd through Wd ---------------------
__global__ void bias2_kernel(const float* __restrict__ Wd, const float* __restrict__ bd,
                             const float* __restrict__ bo_f, const float* __restrict__ bo_b) {
    int o = threadIdx.x;   // 512 threads
    float s = bd[o];
    for (int dd = 0; dd < 512; dd++) {
        s += bo_f[dd] * Wd[dd * 512 + o];
        s += bo_b[dd] * Wd[(512 + dd) * 512 + o];
    }
    g_bias2[o] = s;
}

// ---------------- generic SGEMM: C[m][n] = A[m][k]*B[k][n] + bias[n] --------
#define TBM 128
#define TBN 128
#define TBK 16
__global__ void __launch_bounds__(256, 2)
sgemm(const float* __restrict__ A, const float* __restrict__ B,
      const float* __restrict__ bias, float* __restrict__ C,
      int M, int N, int K) {
    __shared__ float As[TBK][TBM + 4];
    __shared__ float Bs[TBK][TBN + 4];

    int tid = threadIdx.x;
    int bx = blockIdx.x, by = blockIdx.y;
    int tx = tid & 15, ty = tid >> 4;

    int mA  = tid >> 2;       // 0..63 (two rows: mA, mA+64)
    int kcA = tid & 3;        // float4 chunk along K
    int kbB = tid >> 5;       // 0..7 (two rows: kbB, kbB+8)
    int ncB = tid & 31;       // float4 chunk along N

    ull acc[8][4];
    #pragma unroll
    for (int i = 0; i < 8; i++)
        #pragma unroll
        for (int j = 0; j < 4; j++) acc[i][j] = 0ull;

    const float* Ag = A + (size_t)(by * TBM + mA) * K + kcA * 4;
    const float* Bg = B + (size_t)kbB * N + bx * TBN + ncB * 4;

    for (int k0 = 0; k0 < K; k0 += TBK) {
        float4 a0 = *(const float4*)(Ag + k0);
        float4 a1 = *(const float4*)(Ag + (size_t)64 * K + k0);
        float4 b0 = *(const float4*)(Bg + (size_t)k0 * N);
        float4 b1 = *(const float4*)(Bg + (size_t)(k0 + 8) * N);

        __syncthreads();
        As[kcA * 4 + 0][mA] = a0.x;  As[kcA * 4 + 1][mA] = a0.y;
        As[kcA * 4 + 2][mA] = a0.z;  As[kcA * 4 + 3][mA] = a0.w;
        As[kcA * 4 + 0][mA + 64] = a1.x;  As[kcA * 4 + 1][mA + 64] = a1.y;
        As[kcA * 4 + 2][mA + 64] = a1.z;  As[kcA * 4 + 3][mA + 64] = a1.w;
        *(float4*)&Bs[kbB][ncB * 4]     = b0;
        *(float4*)&Bs[kbB + 8][ncB * 4] = b1;
        __syncthreads();

        #pragma unroll
        for (int kk = 0; kk < TBK; kk++) {
            float4 al = *(float4*)&As[kk][ty * 8];
            float4 ah = *(float4*)&As[kk][ty * 8 + 4];
            float4 bl = *(float4*)&Bs[kk][tx * 8];
            float4 bh = *(float4*)&Bs[kk][tx * 8 + 4];
            ull bb[4] = { pk2(bl.x, bl.y), pk2(bl.z, bl.w),
                          pk2(bh.x, bh.y), pk2(bh.z, bh.w) };
            float av[8] = { al.x, al.y, al.z, al.w, ah.x, ah.y, ah.z, ah.w };
            #pragma unroll
            for (int i = 0; i < 8; i++) {
                ull ad = pk2(av[i], av[i]);
                #pragma unroll
                for (int jn = 0; jn < 4; jn++) fm2(acc[i][jn], ad, bb[jn]);
            }
        }
    }

    int mBase = by * TBM + ty * 8;
    int nBase = bx * TBN + tx * 8;
    float4 bvl = make_float4(0.f, 0.f, 0.f, 0.f), bvh = bvl;
    if (bias) {
        bvl = *(const float4*)(bias + nBase);
        bvh = *(const float4*)(bias + nBase + 4);
    }
    #pragma unroll
    for (int i = 0; i < 8; i++) {
        float2 p0 = up2(acc[i][0]), p1 = up2(acc[i][1]);
        float2 p2 = up2(acc[i][2]), p3 = up2(acc[i][3]);
        float4 c0 = make_float4(p0.x + bvl.x, p0.y + bvl.y, p1.x + bvl.z, p1.y + bvl.w);
        float4 c1 = make_float4(p2.x + bvh.x, p2.y + bvh.y, p3.x + bvh.z, p3.y + bvh.w);
        float* cp = C + (size_t)(mBase + i) * N + nBase;
        *(float4*)cp = c0;
        *(float4*)(cp + 4) = c1;
    }
}

// ---------------- recurrence: 16 clusters x 8 CTAs, bulk-copy dataflow ------
// hbuf layout: [buf2][kq8][batch2][64]  (peer r's slice = contiguous 512B)
// Compute: thread (j=tid&63, kq=tid>>6), warp-uniform kq -> broadcast LDS.
// Reduce: part[] SMEM, 128 threads, tanh, write 512B staging.
// Exchange: tid0 issues 8x cp.async.bulk.shared::cluster (512B) completing on
// peers' double-buffered tx mbarriers (expect_tx=4096). No barrier.cluster
// in the loop (no L1D flush), 8 packets + 8 tx updates per step.

__device__ __forceinline__ void mbar_wait_tx(uint32_t mbar, uint32_t parity) {
    uint32_t done;
    asm volatile("{\n\t.reg .pred p;\n\t"
                 "mbarrier.try_wait.parity.acquire.cta.shared::cta.b64 p, [%1], %2;\n\t"
                 "selp.b32 %0, 1, 0, p;\n\t}"
                 : "=r"(done) : "r"(mbar), "r"(parity) : "memory");
    if (!done) {
        asm volatile("{\n\t.reg .pred P1;\n\t"
                     "WL_%=:\n\t"
                     "mbarrier.try_wait.parity.acquire.cta.shared::cta.b64 P1, [%0], %1, 0x989680;\n\t"
                     "@P1 bra.uni WD_%=;\n\t"
                     "bra.uni WL_%=;\n\t"
                     "WD_%=:\n\t}"
                     :: "r"(mbar), "r"(parity) : "memory");
    }
}

__global__ void __launch_bounds__(512, 1) __cluster_dims__(8, 1, 1)
rnn_scan(const float* __restrict__ Wh_f, const float* __restrict__ Wh_b) {
    __shared__ __align__(16) float hbuf[2048];   // [buf2][kq8][b2][64] = 8KB
    __shared__ __align__(16) float part[1024];   // [kq*2+b][64]
    __shared__ __align__(16) float stage[256];   // [par2][b2][64] = 2x512B
    __shared__ __align__(8)  ull  mb[2];

    int tid  = threadIdx.x;
    int bid  = blockIdx.x;
    int rank = bid & 7;
    int cid  = bid >> 3;
    int dir  = cid >> 3;
    int b0   = (cid & 7) * 2;
    int jbase = rank * 64;
    const float* __restrict__ Wh = dir ? Wh_b : Wh_f;

    int j  = tid & 63;
    int kq = tid >> 6;          // warp-uniform
    int kb = kq * 64;
    int jg = jbase + j;

    // weights: 32 packed (k,k+1) pairs for column jg, k in [kb, kb+64)
    ull w[32];
    #pragma unroll
    for (int c = 0; c < 32; c++)
        w[c] = pk2(__ldg(&Wh[(size_t)(kb + 2*c) * H_ + jg]),
                   __ldg(&Wh[(size_t)(kb + 2*c + 1) * H_ + jg]));

    for (int i = tid; i < 2048; i += 512) hbuf[i] = 0.f;

    uint32_t hb_s = (uint32_t)__cvta_generic_to_shared(hbuf);
    uint32_t st_s = (uint32_t)__cvta_generic_to_shared(stage);
    uint32_t mb_s = (uint32_t)__cvta_generic_to_shared(mb);

    if (tid == 0) {
        asm volatile("mbarrier.init.shared.b64 [%0], 1;" :: "r"(mb_s)     : "memory");
        asm volatile("mbarrier.init.shared.b64 [%0], 1;" :: "r"(mb_s + 8) : "memory");
        // pre-arm: mb[1] guards step-1 data (sent during step 0),
        //          mb[0] guards step-2 data (sent during step 1)
        asm volatile("mbarrier.arrive.expect_tx.shared.b64 _, [%0], %1;"
                     :: "r"(mb_s + 8), "r"(4096u) : "memory");
        asm volatile("mbarrier.arrive.expect_tx.shared.b64 _, [%0], %1;"
                     :: "r"(mb_s), "r"(4096u) : "memory");
    }
    __syncthreads();
    asm volatile("barrier.cluster.arrive.aligned;" ::: "memory");
    asm volatile("barrier.cluster.wait.aligned;"   ::: "memory");

    uint32_t pb[8];
    #pragma unroll
    for (int r = 0; r < 8; r++)
        asm("mapa.shared::cluster.u32 %0, %1, %2;" : "=r"(pb[r]) : "r"(hb_s), "r"(r));
    uint32_t dmb = mb_s - hb_s;

    // reduce-role pointers (threads 0..127)
    int rj = tid & 63, rb = (tid >> 6) & 1;
    const float* prer = &g_pre[(size_t)(b0 + rb) * L_ * 1024 + dir * 512 + jbase + rj];
    float*       hsr  = &g_hs [(size_t)(b0 + rb) * L_ * 1024 + dir * 512 + jbase + rj];
    int t0 = dir ? (L_ - 1) : 0;
    float pv = (tid < 128) ? __ldg(prer + (size_t)t0 * 1024) : 0.f;

    for (int s = 0; s < L_; s++) {
        int t = dir ? (L_ - 1 - s) : s;

        if (s) {
            uint32_t par = (s & 1) ? ((s >> 1) & 1) : (((s >> 1) + 1) & 1);
            mbar_wait_tx(mb_s + 8 * (s & 1), par);
            if (tid == 0 && s + 2 < L_)   // re-arm this buffer for step s+2
                asm volatile("mbarrier.arrive.expect_tx.shared.b64 _, [%0], %1;"
                             :: "r"(mb_s + 8 * (s & 1)), "r"(4096u) : "memory");
        }

        // prefetch next step's pre (hidden under compute)
        float nv = 0.f;
        if (tid < 128 && s + 1 < L_) {
            int tn = dir ? (L_ - 2 - s) : (s + 1);
            nv = __ldg(prer + (size_t)tn * 1024);
        }

        // ---- partial dots: k in [kb, kb+64), both batches (broadcast LDS) --
        const float* hp = hbuf + (s & 1) * 1024 + kq * 128;
        ull a0 = 0ull, a1 = 0ull, a2 = 0ull, a3 = 0ull;
        #pragma unroll
        for (int c = 0; c < 16; c++) {
            float4 h0 = *(const float4*)(hp + 4 * c);         // batch 0
            float4 h1 = *(const float4*)(hp + 64 + 4 * c);    // batch 1
            fm2(a0, w[2*c],     pk2(h0.x, h0.y));
            fm2(a1, w[2*c + 1], pk2(h0.z, h0.w));
            fm2(a2, w[2*c],     pk2(h1.x, h1.y));
            fm2(a3, w[2*c + 1], pk2(h1.z, h1.w));
        }
        float2 u0 = up2(a0), u1 = up2(a1), u2 = up2(a2), u3 = up2(a3);
        part[(kq * 2 + 0) * 64 + j] = (u0.x + u0.y) + (u1.x + u1.y);
        part[(kq * 2 + 1) * 64 + j] = (u2.x + u2.y) + (u3.x + u3.y);
        __syncthreads();

        // ---- reduce + tanh + history + staging ----
        if (tid < 128) {
            float sum = pv;
            #pragma unroll
            for (int q = 0; q < 8; q++) sum += part[(q * 2 + rb) * 64 + rj];
            float hn = tanhf(sum);
            hsr[(size_t)t * 1024] = hn;
            stage[((s + 1) & 1) * 128 + rb * 64 + rj] = hn;
        }

        if (s + 1 < L_) {
            __syncthreads();
            if (tid == 0) {
                asm volatile("fence.proxy.async.shared::cta;" ::: "memory");
                uint32_t nxt = (uint32_t)((s + 1) & 1);
                uint32_t src = st_s + nxt * 512;
                #pragma unroll
                for (int r = 0; r < 8; r++) {
                    uint32_t dst = pb[r] + nxt * 4096 + (uint32_t)rank * 512;
                    uint32_t bar = pb[r] + dmb + 8 * nxt;
                    asm volatile(
                        "cp.async.bulk.shared::cluster.shared::cta.mbarrier::complete_tx::bytes "
                        "[%0], [%1], %2, [%3];"
                        :: "r"(dst), "r"(src), "r"(512u), "r"(bar) : "memory");
                }
            }
        }
        pv = nv;
    }
    // exit rendezvous: everyone passed the last wait -> all transfers done
    asm volatile("barrier.cluster.arrive.aligned;" ::: "memory");
    asm volatile("barrier.cluster.wait.aligned;"   ::: "memory");
}

// ---------------- host ------------------------------------------------------
extern "C" void kernel_launch(void* const* d_in, const int* in_sizes, int n_in,
                              void* d_out, int out_size) {
    const float* x    = (const float*)d_in[0];
    // d_in[1] = c (unused by reference)
    const float* Wx_f = (const float*)d_in[2];
    const float* Wh_f = (const float*)d_in[3];
    const float* b_f  = (const float*)d_in[4];
    const float* Wo_f = (const float*)d_in[5];
    const float* bo_f = (const float*)d_in[6];
    const float* Wx_b = (const float*)d_in[7];
    const float* Wh_b = (const float*)d_in[8];
    const float* b_b  = (const float*)d_in[9];
    const float* Wo_b = (const float*)d_in[10];
    const float* bo_b = (const float*)d_in[11];
    const float* Wd   = (const float*)d_in[12];
    const float* bd   = (const float*)d_in[13];
    float* out = (float*)d_out;

    void *p_pre, *p_hs, *p_wx, *p_bc, *p_wc, *p_b2;
    cudaGetSymbolAddress(&p_pre, g_pre);
    cudaGetSymbolAddress(&p_hs,  g_hs);
    cudaGetSymbolAddress(&p_wx,  g_wxcat);
    cudaGetSymbolAddress(&p_bc,  g_bcat);
    cudaGetSymbolAddress(&p_wc,  g_wcomb);
    cudaGetSymbolAddress(&p_b2,  g_bias2);

    // 0) pack Wx / biases
    pack_kernel<<<1024, 512>>>(Wx_f, Wx_b, b_f, b_b);

    // 1) pre = x @ Wxcat + bcat     [32768,512]@[512,1024]
    {
        dim3 g(1024 / TBN, (B_ * L_) / TBM);
        sgemm<<<g, 256>>>(x, (const float*)p_wx, (const float*)p_bc,
                          (float*)p_pre, B_ * L_, 1024, 512);
    }

    // 2,3) Wcomb = [Wo_f@Wd_top ; Wo_b@Wd_bot]
    {
        dim3 g(512 / TBN, 512 / TBM);
        sgemm<<<g, 256>>>(Wo_f, Wd, nullptr, (float*)p_wc, 512, 512, 512);
        sgemm<<<g, 256>>>(Wo_b, Wd + 512 * 512, nullptr,
                          (float*)p_wc + 512 * 512, 512, 512, 512);
    }
    // 4) bias2
    bias2_kernel<<<1, 512>>>(Wd, bd, bo_f, bo_b);

    // 5) bidirectional scan
    {
        cudaLaunchConfig_t cfg = {};
        cfg.gridDim = dim3(128, 1, 1);
        cfg.blockDim = dim3(512, 1, 1);
        cfg.dynamicSmemBytes = 0;
        cfg.stream = 0;
        cudaLaunchAttribute at[1];
        at[0].id = cudaLaunchAttributeClusterDimension;
        at[0].val.clusterDim.x = 8; at[0].val.clusterDim.y = 1; at[0].val.clusterDim.z = 1;
        cfg.attrs = at;
        cfg.numAttrs = 1;
        cudaLaunchKernelEx(&cfg, rnn_scan, Wh_f, Wh_b);
    }

    // 6) out = hs @ Wcomb + bias2   [32768,1024]@[1024,512]
    {
        dim3 g(512 / TBN, (B_ * L_) / TBM);
        sgemm<<<g, 256>>>((const float*)p_hs, (const float*)p_wc,
                          (const float*)p_b2, out, B_ * L_, 512, 1024);
    }
}